// round 2
// baseline (speedup 1.0000x reference)
#include <cuda_runtime.h>

// Problem dims
#define HH 160
#define WW 160
#define DD 96
#define NB 2
#define NC 4
#define BC 8            // NB*NC
#define HO 154
#define WO 154
#define DO2 90
#define WIN 7

#define NVOX_Y (NB*HH*WW*DD)            // 4,915,200
#define A_ELEMS (BC*HH*WW*DO2)          // 18,432,000
#define B_ELEMS (BC*HH*WO*DO2)          // 17,740,800
#define N_OUT   (BC*HO*WO*DO2)          // 17,074,080

#define COV_NORM 1.0208333333333333f    // 49/48
#define CCONST   4.5e-4f                // (0.03)^2/2
#define INV343   (1.0f/343.0f)

// Static scratch (allocation-guard-safe)
__device__ float gA1[A_ELEMS];
__device__ float gA2[A_ELEMS];
__device__ float gA3[A_ELEMS];
__device__ float gB1[B_ELEMS];
__device__ float gB2[B_ELEMS];
__device__ float gB3[B_ELEMS];
__device__ unsigned char gYm[NVOX_Y];
__device__ double g_acc;

// ---------------- kernel 0a: zero accumulator ----------------
__global__ void k_zero() { g_acc = 0.0; }

// ---------------- kernel 0b: y int32 -> uint8 ----------------
// NOTE: reference asks for int64 but JAX x64 is disabled by default, so the
// materialized input is int32. Reading int64 here caused the R1 OOB crash.
__global__ void k_conv(const int* __restrict__ y) {
    int i = blockIdx.x * blockDim.x + threadIdx.x;
    if (i < NVOX_Y) gYm[i] = (unsigned char)y[i];
}

// ---------------- pass 1: fields + 7-window along D ----------------
// block: (96, 4) -> 4 lines of (bc,h,w) per block
__global__ void k_pass1(const float* __restrict__ x) {
    __shared__ float s1[4][DD];
    __shared__ float s2[4][DD];
    __shared__ float s3[4][DD];
    int d  = threadIdx.x;            // 0..95
    int ly = threadIdx.y;            // 0..3
    int lg = blockIdx.x * 4 + ly;    // line index over BC*H*W = 204800
    int hw = lg % (HH * WW);
    int c  = (lg / (HH * WW)) % NC;
    int b  = lg / (NC * HH * WW);

    float xv = x[lg * DD + d];
    unsigned char yv = gYm[(b * HH * WW + hw) * DD + d];
    float sg = 1.0f / (1.0f + __expf(-xv));
    bool m = (yv == (unsigned char)c);
    s1[ly][d] = m ? 1.0f : 0.0f;
    s2[ly][d] = m ? sg : 0.0f;
    s3[ly][d] = m ? sg * sg : 0.0f;
    __syncthreads();

    if (d < DO2) {
        float a = 0.f, bsum = 0.f, cs = 0.f;
        #pragma unroll
        for (int j = 0; j < WIN; j++) {
            a    += s1[ly][d + j];
            bsum += s2[ly][d + j];
            cs   += s3[ly][d + j];
        }
        int o = lg * DO2 + d;
        gA1[o] = a; gA2[o] = bsum; gA3[o] = cs;
    }
}

// ---------------- pass 2: 7-window along W ----------------
// one block per (bc,h); thread = d' (96 threads, 90 active)
__global__ void k_pass2() {
    int d = threadIdx.x;
    if (d >= DO2) return;
    int h  = blockIdx.x % HH;
    int bc = blockIdx.x / HH;
    int ibase = (bc * HH + h) * WW;
    int obase = (bc * HH + h) * WO;

    float s1 = 0.f, s2 = 0.f, s3 = 0.f;
    for (int w = 0; w < WW; w++) {
        int idx = (ibase + w) * DO2 + d;
        s1 += gA1[idx]; s2 += gA2[idx]; s3 += gA3[idx];
        if (w >= WIN) {
            int idx2 = (ibase + w - WIN) * DO2 + d;   // L1-hot re-read
            s1 -= gA1[idx2]; s2 -= gA2[idx2]; s3 -= gA3[idx2];
        }
        if (w >= WIN - 1) {
            int o = (obase + (w - (WIN - 1))) * DO2 + d;
            gB1[o] = s1; gB2[o] = s2; gB3[o] = s3;
        }
    }
}

__inline__ __device__ float warpReduceSum(float v) {
    #pragma unroll
    for (int o = 16; o > 0; o >>= 1) v += __shfl_down_sync(0xffffffffu, v, o);
    return v;
}

// ---------------- pass 3: 7-window along H + s_value + reduction ----------------
// thread = (bc, w', d'); loops h
__global__ void k_pass3() {
    int i = blockIdx.x * blockDim.x + threadIdx.x;
    float local = 0.f;
    if (i < BC * WO * DO2) {
        int bc = i / (WO * DO2);
        int j  = i % (WO * DO2);
        int w  = j / DO2;
        int dd = j % DO2;
        float s1 = 0.f, s2 = 0.f, s3 = 0.f;
        for (int h = 0; h < HH; h++) {
            int idx = ((bc * HH + h) * WO + w) * DO2 + dd;
            s1 += gB1[idx]; s2 += gB2[idx]; s3 += gB3[idx];
            if (h >= WIN) {
                int idx2 = ((bc * HH + h - WIN) * WO + w) * DO2 + dd;
                s1 -= gB1[idx2]; s2 -= gB2[idx2]; s3 -= gB3[idx2];
            }
            if (h >= WIN - 1) {
                float Sy  = s1;
                float Sx  = s2 + 0.5f * (343.0f - s1);
                float Sxx = s3 + 0.25f * (343.0f - s1);
                float Sxy = s2;
                float ux = Sx * INV343, uy = Sy * INV343;
                float vx  = COV_NORM * (Sxx * INV343 - ux * ux);
                float vy  = COV_NORM * (Sy  * INV343 - uy * uy);
                float vxy = COV_NORM * (Sxy * INV343 - ux * uy);
                local += (vxy + CCONST) / (vx * vy + CCONST);
            }
        }
    }
    // block reduce (128 threads = 4 warps)
    __shared__ float wsum[4];
    float v = warpReduceSum(local);
    int lane = threadIdx.x & 31, wid = threadIdx.x >> 5;
    if (lane == 0) wsum[wid] = v;
    __syncthreads();
    if (wid == 0) {
        v = (lane < 4) ? wsum[lane] : 0.f;
        v = warpReduceSum(v);
        if (lane == 0) atomicAdd(&g_acc, (double)v);
    }
}

// ---------------- final ----------------
__global__ void k_final(float* out) {
    out[0] = 1.0f - (float)(g_acc * (1.0 / (double)N_OUT));
}

extern "C" void kernel_launch(void* const* d_in, const int* in_sizes, int n_in,
                              void* d_out, int out_size) {
    const float* x = (const float*)d_in[0];
    const int* y = (const int*)d_in[1];
    float* out = (float*)d_out;

    k_zero<<<1, 1>>>();
    k_conv<<<(NVOX_Y + 255) / 256, 256>>>(y);
    {
        dim3 blk(96, 4);
        int nlines = BC * HH * WW;          // 204800
        k_pass1<<<nlines / 4, blk>>>(x);
    }
    k_pass2<<<BC * HH, 96>>>();
    {
        int total = BC * WO * DO2;          // 110880
        k_pass3<<<(total + 127) / 128, 128>>>();
    }
    k_final<<<1, 1>>>(out);
}